// round 1
// baseline (speedup 1.0000x reference)
#include <cuda_runtime.h>

// ---------------- problem constants ----------------
#define IMG_H 256
#define IMG_W 256
#define BATCH 4
#define HW (IMG_H * IMG_W)

#define TW 32
#define TH 8
#define COUT_PT 16
#define CIN_CHUNK 8

// ---------------- scratch (device globals; no allocs allowed) ----------------
__device__ float g_fea1[BATCH * 64 * HW];
__device__ float g_bufA[BATCH * 64 * HW];
__device__ float g_bufB[BATCH * 64 * HW];
__device__ float g_bufC[BATCH * 64 * HW];
__device__ float g_core[BATCH * 75 * HW];
__device__ float g_res [BATCH * 3  * HW];

// ---------------- generic fused 3x3 SAME conv ----------------
// out[b,co,h,w] = act( beta*out + sum_ci in[b,ci,:,:] (*) wgt[co, cinw0+ci, :, :] + bias[co] ) + addsrc
// ACT: 0 none, 1 relu, 2 leaky-relu(0.1)
template <int ACT>
__global__ __launch_bounds__(256)
void conv3x3_kernel(const float* __restrict__ in, const float* __restrict__ wgt,
                    const float* __restrict__ bias, const float* __restrict__ addsrc,
                    float* __restrict__ out,
                    int CinBuf,   // channels in the input buffer
                    int CinW,     // channel stride in the weight tensor
                    int cinw0,    // starting input-channel offset inside the weight tensor
                    int Cout,     // output channels
                    int beta)     // 1 -> accumulate into existing out
{
    __shared__ float s_in[CIN_CHUNK][TH + 2][TW + 2];
    __shared__ float s_w[COUT_PT][CIN_CHUNK][12];  // 9 taps padded to 12 for float4 loads

    const int tx = threadIdx.x, ty = threadIdx.y;
    const int tid = ty * 32 + tx;
    const int w0 = blockIdx.x * TW;
    const int by = blockIdx.y;
    const int b = by >> 5;            // IMG_H/TH = 32 tiles per image
    const int h0 = (by & 31) * TH;
    const int coBase = blockIdx.z * COUT_PT;

    float acc[COUT_PT];
#pragma unroll
    for (int i = 0; i < COUT_PT; i++) acc[i] = 0.f;

    for (int cin0 = 0; cin0 < CinBuf; cin0 += CIN_CHUNK) {
        const int cc = min(CIN_CHUNK, CinBuf - cin0);
        __syncthreads();

        // ---- load input halo tile (cc channels) ----
        for (int ci = 0; ci < cc; ci++) {
            const float* ip = in + (size_t)(b * CinBuf + cin0 + ci) * HW;
            for (int j = tid; j < (TH + 2) * (TW + 2); j += 256) {
                int r = j / (TW + 2);
                int c = j - r * (TW + 2);
                int hh = h0 - 1 + r;
                int ww = w0 - 1 + c;
                float v = 0.f;
                if (hh >= 0 && hh < IMG_H && ww >= 0 && ww < IMG_W) v = ip[hh * IMG_W + ww];
                s_in[ci][r][c] = v;
            }
        }
        // ---- load weights (COUT_PT x cc x 9, zero-padded) ----
        for (int j = tid; j < COUT_PT * CIN_CHUNK * 9; j += 256) {
            int co = j / (CIN_CHUNK * 9);
            int rem = j - co * (CIN_CHUNK * 9);
            int ci = rem / 9;
            int k = rem - ci * 9;
            float v = 0.f;
            int cog = coBase + co;
            if (ci < cc && cog < Cout)
                v = wgt[((size_t)cog * CinW + (cinw0 + cin0 + ci)) * 9 + k];
            s_w[co][ci][k] = v;
        }
        __syncthreads();

        // ---- compute ----
        auto body = [&](int ci) {
            float v0 = s_in[ci][ty + 0][tx + 0];
            float v1 = s_in[ci][ty + 0][tx + 1];
            float v2 = s_in[ci][ty + 0][tx + 2];
            float v3 = s_in[ci][ty + 1][tx + 0];
            float v4 = s_in[ci][ty + 1][tx + 1];
            float v5 = s_in[ci][ty + 1][tx + 2];
            float v6 = s_in[ci][ty + 2][tx + 0];
            float v7 = s_in[ci][ty + 2][tx + 1];
            float v8 = s_in[ci][ty + 2][tx + 2];
#pragma unroll
            for (int co = 0; co < COUT_PT; co++) {
                float4 wa = *(const float4*)&s_w[co][ci][0];
                float4 wb = *(const float4*)&s_w[co][ci][4];
                float w8 = s_w[co][ci][8];
                float s = acc[co];
                s += v0 * wa.x; s += v1 * wa.y; s += v2 * wa.z; s += v3 * wa.w;
                s += v4 * wb.x; s += v5 * wb.y; s += v6 * wb.z; s += v7 * wb.w;
                s += v8 * w8;
                acc[co] = s;
            }
        };
        if (cc == CIN_CHUNK) {
#pragma unroll
            for (int ci = 0; ci < CIN_CHUNK; ci++) body(ci);
        } else {
            for (int ci = 0; ci < cc; ci++) body(ci);
        }
    }

    // ---- epilogue ----
    const int hh = h0 + ty;
    const int ww = w0 + tx;
#pragma unroll
    for (int co = 0; co < COUT_PT; co++) {
        int cog = coBase + co;
        if (cog >= Cout) break;
        size_t idx = (size_t)(b * Cout + cog) * HW + hh * IMG_W + ww;
        float v = acc[co];
        if (beta) v += out[idx];
        if (bias) v += __ldg(&bias[cog]);
        if (ACT == 1) v = fmaxf(v, 0.f);
        else if (ACT == 2) v = (v >= 0.f) ? v : 0.1f * v;
        if (addsrc) v += addsrc[idx];
        out[idx] = v;
    }
}

// ---------------- elementwise add: a += b ----------------
__global__ void add_kernel(float* __restrict__ a, const float* __restrict__ b, int n)
{
    int i = blockIdx.x * blockDim.x + threadIdx.x;
    if (i < n) a[i] += b[i];
}

// ---------------- KPN: per-pixel 5x5 kernels + residual ----------------
__global__ void kpn_kernel(const float* __restrict__ x, const float* __restrict__ core,
                           const float* __restrict__ res, float* __restrict__ out)
{
    int idx = blockIdx.x * blockDim.x + threadIdx.x;
    if (idx >= BATCH * 3 * HW) return;
    int w = idx & (IMG_W - 1);
    int h = (idx >> 8) & (IMG_H - 1);
    int bc = idx >> 16;             // b*3 + c
    int c = bc % 3;
    int b = bc / 3;

    const float* xp = x + (size_t)bc * HW;
    const float* cp = core + (size_t)(b * 75 + c * 25) * HW + h * IMG_W + w;

    float s = 0.f;
#pragma unroll
    for (int ky = 0; ky < 5; ky++) {
        int hh = h + ky - 2;
#pragma unroll
        for (int kx = 0; kx < 5; kx++) {
            int ww = w + kx - 2;
            float xv = (hh >= 0 && hh < IMG_H && ww >= 0 && ww < IMG_W) ? xp[hh * IMG_W + ww] : 0.f;
            s += xv * cp[(ky * 5 + kx) * HW];
        }
    }
    out[idx] = s + res[idx];
}

// ---------------- host-side helpers ----------------
static void launch_conv(const float* in, const float* wgt, const float* bias,
                        const float* addsrc, float* out,
                        int CinBuf, int CinW, int cinw0, int Cout, int beta, int act)
{
    dim3 grid(IMG_W / TW, (IMG_H / TH) * BATCH, (Cout + COUT_PT - 1) / COUT_PT);
    dim3 blk(32, 8);
    if (act == 0)
        conv3x3_kernel<0><<<grid, blk>>>(in, wgt, bias, addsrc, out, CinBuf, CinW, cinw0, Cout, beta);
    else if (act == 1)
        conv3x3_kernel<1><<<grid, blk>>>(in, wgt, bias, addsrc, out, CinBuf, CinW, cinw0, Cout, beta);
    else
        conv3x3_kernel<2><<<grid, blk>>>(in, wgt, bias, addsrc, out, CinBuf, CinW, cinw0, Cout, beta);
}

extern "C" void kernel_launch(void* const* d_in, const int* in_sizes, int n_in,
                              void* d_out, int out_size)
{
    const float* x       = (const float*)d_in[0];
    const float* w_first = (const float*)d_in[1];
    const float* b_first = (const float*)d_in[2];
    const float* w_trunk = (const float*)d_in[3];
    const float* b_trunk = (const float*)d_in[4];
    const float* c1_w    = (const float*)d_in[5];
    const float* c1_b    = (const float*)d_in[6];
    const float* c2_w1   = (const float*)d_in[7];
    const float* c2_b1   = (const float*)d_in[8];
    const float* c2_w2   = (const float*)d_in[9];
    const float* c2_b2   = (const float*)d_in[10];
    const float* c3_w1   = (const float*)d_in[11];
    const float* c3_b1   = (const float*)d_in[12];
    const float* c3_w2   = (const float*)d_in[13];
    const float* c3_b2   = (const float*)d_in[14];
    const float* c3_w3   = (const float*)d_in[15];
    const float* c3_b3   = (const float*)d_in[16];
    float* out = (float*)d_out;
    (void)in_sizes; (void)n_in; (void)out_size;

    float *fea1, *bufA, *bufB, *bufC, *core, *res;
    cudaGetSymbolAddress((void**)&fea1, g_fea1);
    cudaGetSymbolAddress((void**)&bufA, g_bufA);
    cudaGetSymbolAddress((void**)&bufB, g_bufB);
    cudaGetSymbolAddress((void**)&bufC, g_bufC);
    cudaGetSymbolAddress((void**)&core, g_core);
    cudaGetSymbolAddress((void**)&res,  g_res);

    // 1) fea1 = lrelu(conv_first(x))
    launch_conv(x, w_first, b_first, nullptr, fea1, 3, 3, 0, 64, 0, 2);

    // 2) 16 residual blocks (ping-pong A/B, tmp C)
    const float* cur = fea1;
    for (int i = 0; i < 16; i++) {
        const float* w1 = w_trunk + (size_t)(i * 2 + 0) * 64 * 64 * 9;
        const float* b1 = b_trunk + (size_t)(i * 2 + 0) * 64;
        const float* w2 = w_trunk + (size_t)(i * 2 + 1) * 64 * 64 * 9;
        const float* b2 = b_trunk + (size_t)(i * 2 + 1) * 64;
        float* dst = (i & 1) ? bufB : bufA;
        launch_conv(cur, w1, b1, nullptr, bufC, 64, 64, 0, 64, 0, 1);    // T = relu(conv1(cur))
        launch_conv(bufC, w2, b2, cur, dst, 64, 64, 0, 64, 0, 0);        // dst = conv2(T) + cur
        cur = dst;
    }
    float* F = (float*)cur;   // bufB after 16 blocks

    // 3) global residual: F += fea1
    add_kernel<<<(BATCH * 64 * HW + 255) / 256, 256>>>(F, fea1, BATCH * 64 * HW);

    // 4) image-feature branch: t3 = conv(relu(conv(relu(conv(x)))))
    float* tA = (F == bufB) ? bufA : bufB;
    launch_conv(x,   c3_w1, c3_b1, nullptr, tA,   3, 3, 0, 64, 0, 1);
    launch_conv(tA,  c3_w2, c3_b2, nullptr, bufC, 64, 64, 0, 64, 0, 1);
    launch_conv(bufC, c3_w3, c3_b3, nullptr, tA,  64, 64, 0, 64, 0, 0);  // t3 in tA

    // 5) residual branch: R1 = relu(conv(concat[t3, F], c2_w1)) -- two accumulating passes
    launch_conv(tA, c2_w1, nullptr, nullptr, bufC, 64, 128, 0,  64, 0, 0);
    launch_conv(F,  c2_w1, c2_b1,  nullptr, bufC, 64, 128, 64, 64, 1, 1);
    // residual = conv(R1, c2_w2)
    launch_conv(bufC, c2_w2, c2_b2, nullptr, res, 64, 64, 0, 3, 0, 0);

    // 6) core = conv(concat[t3, F], c1_w) -- two accumulating passes
    launch_conv(tA, c1_w, nullptr, nullptr, core, 64, 128, 0,  75, 0, 0);
    launch_conv(F,  c1_w, c1_b,   nullptr, core, 64, 128, 64, 75, 1, 0);

    // 7) KPN apply + residual
    kpn_kernel<<<(BATCH * 3 * HW + 255) / 256, 256>>>(x, core, res, out);
}